// round 9
// baseline (speedup 1.0000x reference)
#include <cuda_runtime.h>
#include <cuda_fp16.h>
#include <cuda_bf16.h>
#include <mma.h>
#include <cstdint>

using namespace nvcuda;

#define N_NODES 131072
#define P_NODES 4096
#define B_GR    32
#define E_EDGES 2097152
#define IN_DIM  64
#define HID     128
#define OUT_DIM 16
#define CAP     64
#define EPSV    1e-5f
#define SLOPE   0.01f

// ---------------- scratch (device globals; no allocations allowed) ----------
__device__ int    g_deg_src[N_NODES];
__device__ int    g_cursor[N_NODES];                 // dst degree after build
__device__ float  g_rs_src[N_NODES];
__device__ int2   g_csre[(size_t)N_NODES * CAP];     // packed {src, raw ew}
__device__ __nv_bfloat16 g_x16[(size_t)N_NODES * IN_DIM];   // bf16 features
__device__ __nv_bfloat16 g_agg1[(size_t)N_NODES * IN_DIM];
__device__ __nv_bfloat16 g_agg2[(size_t)N_NODES * HID];
__device__ __nv_bfloat16 g_w1t[HID * IN_DIM];        // W1^T  [n][k]
__device__ __nv_bfloat16 g_w2t[HID * HID];           // W2^T  [n][k]
__device__ float  g_h1pre[(size_t)N_NODES * HID];
__device__ __half g_h1h[(size_t)N_NODES * HID];      // normalized h1 fp16
__device__ float  g_h2pre[(size_t)N_NODES * HID];
__device__ float  g_stats1[2 * HID];
__device__ float  g_stats2[2 * HID];
__device__ float  g_r[B_GR * 2 * HID];

// ---------------- setup -----------------------------------------------------

__global__ void k_zero() {
    int i = blockIdx.x * blockDim.x + threadIdx.x;
    if (i < N_NODES) { g_deg_src[i] = 0; g_cursor[i] = 0; }
    if (i < 2 * HID) { g_stats1[i] = 0.f; g_stats2[i] = 0.f; }
    if (i < B_GR * 2 * HID) { g_r[i] = 0.f; }
}

// 4 edges/thread: vector loads + 4 independent atomic chains (latency hiding).
// Writes packed {src, raw ew} directly into CSR slots.
__global__ __launch_bounds__(256) void k_build(const int* __restrict__ src,
                                               const int* __restrict__ dst,
                                               const float* __restrict__ ew) {
    int e4 = (blockIdx.x * 256 + threadIdx.x) * 4;
    int4   s4 = *(const int4*)&src[e4];
    int4   d4 = *(const int4*)&dst[e4];
    float4 w4 = *(const float4*)&ew[e4];
    int p0 = atomicAdd(&g_cursor[d4.x], 1);
    int p1 = atomicAdd(&g_cursor[d4.y], 1);
    int p2 = atomicAdd(&g_cursor[d4.z], 1);
    int p3 = atomicAdd(&g_cursor[d4.w], 1);
    atomicAdd(&g_deg_src[s4.x], 1);
    atomicAdd(&g_deg_src[s4.y], 1);
    atomicAdd(&g_deg_src[s4.z], 1);
    atomicAdd(&g_deg_src[s4.w], 1);
    if (p0 < CAP) g_csre[(size_t)d4.x * CAP + p0] = make_int2(s4.x, __float_as_int(w4.x));
    if (p1 < CAP) g_csre[(size_t)d4.y * CAP + p1] = make_int2(s4.y, __float_as_int(w4.y));
    if (p2 < CAP) g_csre[(size_t)d4.z * CAP + p2] = make_int2(s4.z, __float_as_int(w4.z));
    if (p3 < CAP) g_csre[(size_t)d4.w * CAP + p3] = make_int2(s4.w, __float_as_int(w4.w));
}

__global__ void k_rs() {
    int v = blockIdx.x * blockDim.x + threadIdx.x;
    if (v < N_NODES) g_rs_src[v] = rsqrtf((float)max(g_deg_src[v], 1));
}

// blocks [0,4096): convert features to bf16 (8 elems/thread).
// block 4096: transpose W1,W2 to bf16 K-major.
__global__ __launch_bounds__(256) void k_prep(const float* __restrict__ x,
                                              const float* __restrict__ W1,
                                              const float* __restrict__ W2) {
    int b = blockIdx.x, t = threadIdx.x;
    if (b < 4096) {
        int i0 = b * 2048 + t * 8;
        float4 a = *(const float4*)&x[i0];
        float4 c = *(const float4*)&x[i0 + 4];
        uint4 o;
        __nv_bfloat162 b0 = __floats2bfloat162_rn(a.x, a.y);
        __nv_bfloat162 b1 = __floats2bfloat162_rn(a.z, a.w);
        __nv_bfloat162 b2 = __floats2bfloat162_rn(c.x, c.y);
        __nv_bfloat162 b3 = __floats2bfloat162_rn(c.z, c.w);
        o.x = *(uint32_t*)&b0; o.y = *(uint32_t*)&b1;
        o.z = *(uint32_t*)&b2; o.w = *(uint32_t*)&b3;
        *(uint4*)&g_x16[i0] = o;
    } else {
        for (int i = t; i < HID * IN_DIM; i += 256) {
            int n = i / IN_DIM, k = i % IN_DIM;
            g_w1t[i] = __float2bfloat16(W1[k * HID + n]);
        }
        for (int i = t; i < HID * HID; i += 256) {
            int n = i / HID, k = i % HID;
            g_w2t[i] = __float2bfloat16(W2[k * HID + n]);
        }
    }
}

// ---------------- aggregation (pure gather) ----------------------------------
// warp per node x4; lane = 2 bf16 features (layer1). rs_src folded at gather.
__global__ __launch_bounds__(256) void k_agg1() {
    int tid = threadIdx.x, w = tid >> 5, lane = tid & 31;
    int vb = blockIdx.x * 32 + w * 4;
    #pragma unroll
    for (int nn = 0; nn < 4; nn++) {
        int v = vb + nn;
        int degf = g_cursor[v];
        int deg  = min(degf, CAP);
        const int2* ce = &g_csre[(size_t)v * CAP];
        float a0 = 0.f, a1 = 0.f;
        for (int i = 0; i < deg; i += 4) {
            int i1 = min(i + 1, deg - 1), i2 = min(i + 2, deg - 1), i3 = min(i + 3, deg - 1);
            int2 e0 = __ldg(&ce[i]);
            int2 e1 = __ldg(&ce[i1]);
            int2 e2 = __ldg(&ce[i2]);
            int2 e3 = __ldg(&ce[i3]);
            float w0 = __int_as_float(e0.y) * g_rs_src[e0.x];
            float w1 = (i + 1 < deg) ? __int_as_float(e1.y) * g_rs_src[e1.x] : 0.f;
            float w2 = (i + 2 < deg) ? __int_as_float(e2.y) * g_rs_src[e2.x] : 0.f;
            float w3 = (i + 3 < deg) ? __int_as_float(e3.y) * g_rs_src[e3.x] : 0.f;
            float2 v0 = __bfloat1622float2(((const __nv_bfloat162*)(g_x16 + (size_t)e0.x * IN_DIM))[lane]);
            float2 v1 = __bfloat1622float2(((const __nv_bfloat162*)(g_x16 + (size_t)e1.x * IN_DIM))[lane]);
            float2 v2 = __bfloat1622float2(((const __nv_bfloat162*)(g_x16 + (size_t)e2.x * IN_DIM))[lane]);
            float2 v3 = __bfloat1622float2(((const __nv_bfloat162*)(g_x16 + (size_t)e3.x * IN_DIM))[lane]);
            a0 += w0 * v0.x + w1 * v1.x + w2 * v2.x + w3 * v3.x;
            a1 += w0 * v0.y + w1 * v1.y + w2 * v2.y + w3 * v3.y;
        }
        float rd = rsqrtf((float)max(degf, 1));
        ((__nv_bfloat162*)&g_agg1[(size_t)v * IN_DIM])[lane] =
            __floats2bfloat162_rn(a0 * rd, a1 * rd);
    }
}

// layer-2 gather from fp16 h1 (lane = 4 features)
__global__ __launch_bounds__(256) void k_agg2() {
    int tid = threadIdx.x, w = tid >> 5, lane = tid & 31;
    int vb = blockIdx.x * 32 + w * 4;
    #pragma unroll
    for (int nn = 0; nn < 4; nn++) {
        int v = vb + nn;
        int degf = g_cursor[v];
        int deg  = min(degf, CAP);
        const int2* ce = &g_csre[(size_t)v * CAP];
        float a0 = 0.f, a1 = 0.f, a2 = 0.f, a3 = 0.f;
        for (int i = 0; i < deg; i += 4) {
            int i1 = min(i + 1, deg - 1), i2 = min(i + 2, deg - 1), i3 = min(i + 3, deg - 1);
            int2 e0 = __ldg(&ce[i]);
            int2 e1 = __ldg(&ce[i1]);
            int2 e2 = __ldg(&ce[i2]);
            int2 e3 = __ldg(&ce[i3]);
            float w0 = __int_as_float(e0.y) * g_rs_src[e0.x];
            float w1 = (i + 1 < deg) ? __int_as_float(e1.y) * g_rs_src[e1.x] : 0.f;
            float w2 = (i + 2 < deg) ? __int_as_float(e2.y) * g_rs_src[e2.x] : 0.f;
            float w3 = (i + 3 < deg) ? __int_as_float(e3.y) * g_rs_src[e3.x] : 0.f;
            uint2 u0 = ((const uint2*)(g_h1h + (size_t)e0.x * HID))[lane];
            uint2 u1 = ((const uint2*)(g_h1h + (size_t)e1.x * HID))[lane];
            uint2 u2 = ((const uint2*)(g_h1h + (size_t)e2.x * HID))[lane];
            uint2 u3 = ((const uint2*)(g_h1h + (size_t)e3.x * HID))[lane];
            float2 p, q;
            p = __half22float2(*(const __half2*)&u0.x); q = __half22float2(*(const __half2*)&u0.y);
            a0 += w0 * p.x; a1 += w0 * p.y; a2 += w0 * q.x; a3 += w0 * q.y;
            p = __half22float2(*(const __half2*)&u1.x); q = __half22float2(*(const __half2*)&u1.y);
            a0 += w1 * p.x; a1 += w1 * p.y; a2 += w1 * q.x; a3 += w1 * q.y;
            p = __half22float2(*(const __half2*)&u2.x); q = __half22float2(*(const __half2*)&u2.y);
            a0 += w2 * p.x; a1 += w2 * p.y; a2 += w2 * q.x; a3 += w2 * q.y;
            p = __half22float2(*(const __half2*)&u3.x); q = __half22float2(*(const __half2*)&u3.y);
            a0 += w3 * p.x; a1 += w3 * p.y; a2 += w3 * q.x; a3 += w3 * q.y;
        }
        float rd = rsqrtf((float)max(degf, 1));
        __nv_bfloat162 b0 = __floats2bfloat162_rn(a0 * rd, a1 * rd);
        __nv_bfloat162 b1 = __floats2bfloat162_rn(a2 * rd, a3 * rd);
        uint2 packed;
        packed.x = *(uint32_t*)&b0;
        packed.y = *(uint32_t*)&b1;
        ((uint2*)&g_agg2[(size_t)v * HID])[lane] = packed;
    }
}

// ---------------- WMMA GEMM + fused GraphNorm stats --------------------------
// 256 threads = 8 warps; warp w owns a 16x128 output strip (8 accum frags).
// Epilogue: accs -> smem (tile space dead), stats reduction + coalesced store.
__global__ __launch_bounds__(256) void k_gemm(int layer) {
    extern __shared__ __nv_bfloat16 smb[];
    const int K   = (layer == 1) ? IN_DIM : HID;
    const int pitch = K + 8;
    __nv_bfloat16* sA = smb;                       // [128][pitch]
    __nv_bfloat16* sB = smb + 128 * pitch;         // [128][pitch]
    const __nv_bfloat16* Ag = (layer == 1) ? g_agg1 : g_agg2;
    const __nv_bfloat16* Bg = (layer == 1) ? g_w1t  : g_w2t;
    int tid = threadIdx.x;
    size_t m0 = (size_t)blockIdx.x * 128;

    int vecs = K / 8;                              // uint4 = 8 bf16
    for (int i = tid; i < 128 * vecs; i += 256) {
        int r = i / vecs, c = i % vecs;
        *(uint4*)&sA[r * pitch + c * 8] = *(const uint4*)&Ag[(m0 + r) * K + c * 8];
        *(uint4*)&sB[r * pitch + c * 8] = *(const uint4*)&Bg[(size_t)r * K + c * 8];
    }
    __syncthreads();

    int w = tid >> 5;
    wmma::fragment<wmma::accumulator, 16, 16, 16, float> acc[8];
    #pragma unroll
    for (int n = 0; n < 8; n++) wmma::fill_fragment(acc[n], 0.f);

    for (int k = 0; k < K; k += 16) {
        wmma::fragment<wmma::matrix_a, 16, 16, 16, __nv_bfloat16, wmma::row_major> fa;
        wmma::load_matrix_sync(fa, &sA[(w * 16) * pitch + k], pitch);
        #pragma unroll
        for (int n = 0; n < 8; n++) {
            wmma::fragment<wmma::matrix_b, 16, 16, 16, __nv_bfloat16, wmma::col_major> fb;
            wmma::load_matrix_sync(fb, &sB[(n * 16) * pitch + k], pitch);
            wmma::mma_sync(acc[n], fa, fb, acc[n]);
        }
    }

    // ---- epilogue: stage to smem, fused stats, coalesced global write ----
    __syncthreads();                               // tiles dead
    float* Hs = (float*)smb;                       // [128][128] = 64 KB
    #pragma unroll
    for (int n = 0; n < 8; n++)
        wmma::store_matrix_sync(&Hs[(w * 16) * HID + n * 16], acc[n], HID,
                                wmma::mem_row_major);
    __syncthreads();

    float* H  = (layer == 1) ? g_h1pre : g_h2pre;
    float* st = (layer == 1) ? g_stats1 : g_stats2;

    int col = tid & 127, half = tid >> 7;          // half-column per thread
    float s = 0.f, ss = 0.f;
    #pragma unroll 8
    for (int r = 0; r < 64; r++) {
        float vv = Hs[(half * 64 + r) * HID + col];
        s += vv;
        ss += vv * vv;
    }
    atomicAdd(&st[col], s);
    atomicAdd(&st[HID + col], ss);

    for (int i = tid; i < 128 * 32; i += 256) {
        int r = i >> 5, c = i & 31;
        ((float4*)&H[(m0 + r) * HID])[c] = ((const float4*)&Hs[r * HID])[c];
    }
}

// ---------------- norm / readout ---------------------------------------------

__global__ void k_norm(int layer,
                       const float* __restrict__ gamma, const float* __restrict__ beta,
                       const float* __restrict__ alpha) {
    int j = threadIdx.x;
    int b = blockIdx.x;
    const float* stats = (layer == 1) ? g_stats1 : g_stats2;
    const float* hpre  = (layer == 1) ? g_h1pre : g_h2pre;
    int rcol   = (layer == 1) ? 0 : HID;
    int writeH = (layer == 1) ? 1 : 0;

    const float invN = 1.0f / (float)N_NODES;
    float mu  = stats[j] * invN;
    float ex2 = stats[HID + j] * invN;
    float al  = alpha[j];
    float var = ex2 + mu * mu * (al * al - 2.f * al);
    float istd = rsqrtf(var + EPSV);
    float ga = gamma[j] * istd;
    float be = beta[j];
    float amu = al * mu;

    int g = (b * 128) / P_NODES;
    const float* in = &hpre[(size_t)b * 128 * HID];
    __half* out = &g_h1h[(size_t)b * 128 * HID];
    float rsum = 0.f;
    #pragma unroll 4
    for (int r = 0; r < 128; r++) {
        float v = in[r * HID + j];
        float c = (v - amu) * ga + be;
        float y = c > 0.f ? c : SLOPE * c;
        if (writeH) out[r * HID + j] = __float2half(y);
        rsum += y;
    }
    atomicAdd(&g_r[g * (2 * HID) + rcol + j], rsum);
}

__global__ void k_final(const float* __restrict__ Wc, float* __restrict__ out) {
    int t = threadIdx.x;
    int b = t >> 4, o = t & 15;
    const float* rb = &g_r[b * 2 * HID];
    const float* wr = &Wc[o * 2 * HID];
    float s = 0.f;
    #pragma unroll 8
    for (int k = 0; k < 2 * HID; k++) s += rb[k] * wr[k];
    out[b * OUT_DIM + o] = s * (1.0f / (float)P_NODES);
}

// ---------------- launch -----------------------------------------------------

extern "C" void kernel_launch(void* const* d_in, const int* in_sizes, int n_in,
                              void* d_out, int out_size) {
    const float* features = (const float*)d_in[0];
    const float* ew       = (const float*)d_in[1];
    const int*   src      = (const int*)d_in[2];
    const int*   dst      = (const int*)d_in[3];
    const float* W1       = (const float*)d_in[4];
    const float* W2       = (const float*)d_in[5];
    const float* Wc       = (const float*)d_in[6];
    const float* gamma1   = (const float*)d_in[7];
    const float* beta1    = (const float*)d_in[8];
    const float* alpha1   = (const float*)d_in[9];
    const float* gamma2   = (const float*)d_in[10];
    const float* beta2    = (const float*)d_in[11];
    const float* alpha2   = (const float*)d_in[12];
    float* out = (float*)d_out;

    // smem: max(tiles, 128x128 fp32 epilogue stage)
    const int smem1 = 128 * 128 * 4;                               // 65536
    const int smem2 = 2 * 128 * (HID + 8) * 2;                     // 69632
    cudaFuncSetAttribute(k_gemm, cudaFuncAttributeMaxDynamicSharedMemorySize, smem2);

    k_zero<<<N_NODES / 256, 256>>>();
    k_build<<<E_EDGES / 1024, 256>>>(src, dst, ew);
    k_rs<<<N_NODES / 256, 256>>>();
    k_prep<<<4097, 256>>>(features, W1, W2);

    k_agg1<<<N_NODES / 32, 256>>>();
    k_gemm<<<N_NODES / 128, 256, smem1>>>(1);
    k_norm<<<1024, 128>>>(1, gamma1, beta1, alpha1);

    k_agg2<<<N_NODES / 32, 256>>>();
    k_gemm<<<N_NODES / 128, 256, smem2>>>(2);
    k_norm<<<1024, 128>>>(2, gamma2, beta2, alpha2);

    k_final<<<1, 512>>>(Wc, out);
}

// round 10
// speedup vs baseline: 1.0805x; 1.0805x over previous
#include <cuda_runtime.h>
#include <cuda_fp16.h>
#include <cuda_bf16.h>
#include <mma.h>
#include <cstdint>

using namespace nvcuda;

#define N_NODES 131072
#define P_NODES 4096
#define B_GR    32
#define E_EDGES 2097152
#define IN_DIM  64
#define HID     128
#define OUT_DIM 16
#define CAP     64
#define EPSV    1e-5f
#define SLOPE   0.01f

// ---------------- scratch (device globals; no allocations allowed) ----------
__device__ int    g_deg_src[N_NODES];
__device__ int    g_cursor[N_NODES];                 // dst degree after build
__device__ float  g_rs_src[N_NODES];
__device__ int2   g_csre[(size_t)N_NODES * CAP];     // packed {src, raw ew}
__device__ __nv_bfloat16 g_x16[(size_t)N_NODES * IN_DIM];   // bf16 features * rs_src
__device__ __nv_bfloat16 g_agg1[(size_t)N_NODES * IN_DIM];
__device__ __nv_bfloat16 g_agg2[(size_t)N_NODES * HID];
__device__ __nv_bfloat16 g_w1t[HID * IN_DIM];        // W1^T  [n][k]
__device__ __nv_bfloat16 g_w2t[HID * HID];           // W2^T  [n][k]
__device__ float  g_h1pre[(size_t)N_NODES * HID];
__device__ __half g_h1h[(size_t)N_NODES * HID];      // normalized h1 * rs_src (fp16)
__device__ float  g_h2pre[(size_t)N_NODES * HID];
__device__ float  g_stats1[2 * HID];
__device__ float  g_stats2[2 * HID];
__device__ float  g_r[B_GR * 2 * HID];

// ---------------- setup -----------------------------------------------------

__global__ void k_zero() {
    int i = blockIdx.x * blockDim.x + threadIdx.x;
    if (i < N_NODES) { g_deg_src[i] = 0; g_cursor[i] = 0; }
    if (i < 2 * HID) { g_stats1[i] = 0.f; g_stats2[i] = 0.f; }
    if (i < B_GR * 2 * HID) { g_r[i] = 0.f; }
}

// 4 edges/thread: vector loads + independent atomic chains; writes packed CSR.
__global__ __launch_bounds__(256) void k_build(const int* __restrict__ src,
                                               const int* __restrict__ dst,
                                               const float* __restrict__ ew) {
    int e4 = (blockIdx.x * 256 + threadIdx.x) * 4;
    int4   s4 = *(const int4*)&src[e4];
    int4   d4 = *(const int4*)&dst[e4];
    float4 w4 = *(const float4*)&ew[e4];
    int p0 = atomicAdd(&g_cursor[d4.x], 1);
    int p1 = atomicAdd(&g_cursor[d4.y], 1);
    int p2 = atomicAdd(&g_cursor[d4.z], 1);
    int p3 = atomicAdd(&g_cursor[d4.w], 1);
    atomicAdd(&g_deg_src[s4.x], 1);
    atomicAdd(&g_deg_src[s4.y], 1);
    atomicAdd(&g_deg_src[s4.z], 1);
    atomicAdd(&g_deg_src[s4.w], 1);
    if (p0 < CAP) g_csre[(size_t)d4.x * CAP + p0] = make_int2(s4.x, __float_as_int(w4.x));
    if (p1 < CAP) g_csre[(size_t)d4.y * CAP + p1] = make_int2(s4.y, __float_as_int(w4.y));
    if (p2 < CAP) g_csre[(size_t)d4.z * CAP + p2] = make_int2(s4.z, __float_as_int(w4.z));
    if (p3 < CAP) g_csre[(size_t)d4.w * CAP + p3] = make_int2(s4.w, __float_as_int(w4.w));
}

__global__ void k_rs() {
    int v = blockIdx.x * blockDim.x + threadIdx.x;
    if (v < N_NODES) g_rs_src[v] = rsqrtf((float)max(g_deg_src[v], 1));
}

// blocks [0,4096): features -> bf16, pre-scaled by rs_src[row] (8 elems/thread).
// block 4096: transpose W1,W2 to bf16 K-major.
__global__ __launch_bounds__(256) void k_prep(const float* __restrict__ x,
                                              const float* __restrict__ W1,
                                              const float* __restrict__ W2) {
    int b = blockIdx.x, t = threadIdx.x;
    if (b < 4096) {
        int i0 = b * 2048 + t * 8;
        int row = i0 >> 6;                          // 64 floats per row
        float rs = g_rs_src[row];
        float4 a = *(const float4*)&x[i0];
        float4 c = *(const float4*)&x[i0 + 4];
        uint4 o;
        __nv_bfloat162 b0 = __floats2bfloat162_rn(a.x * rs, a.y * rs);
        __nv_bfloat162 b1 = __floats2bfloat162_rn(a.z * rs, a.w * rs);
        __nv_bfloat162 b2 = __floats2bfloat162_rn(c.x * rs, c.y * rs);
        __nv_bfloat162 b3 = __floats2bfloat162_rn(c.z * rs, c.w * rs);
        o.x = *(uint32_t*)&b0; o.y = *(uint32_t*)&b1;
        o.z = *(uint32_t*)&b2; o.w = *(uint32_t*)&b3;
        *(uint4*)&g_x16[i0] = o;
    } else {
        for (int i = t; i < HID * IN_DIM; i += 256) {
            int n = i / IN_DIM, k = i % IN_DIM;
            g_w1t[i] = __float2bfloat16(W1[k * HID + n]);
        }
        for (int i = t; i < HID * HID; i += 256) {
            int n = i / HID, k = i % HID;
            g_w2t[i] = __float2bfloat16(W2[k * HID + n]);
        }
    }
}

// ---------------- aggregation (pure gather; weight = raw ew) -----------------
// warp per node x4; lane = 2 bf16 features (layer1).
__global__ __launch_bounds__(256) void k_agg1() {
    int tid = threadIdx.x, w = tid >> 5, lane = tid & 31;
    int vb = blockIdx.x * 32 + w * 4;
    #pragma unroll
    for (int nn = 0; nn < 4; nn++) {
        int v = vb + nn;
        int degf = g_cursor[v];
        int deg  = min(degf, CAP);
        const int2* ce = &g_csre[(size_t)v * CAP];
        float a0 = 0.f, a1 = 0.f;
        for (int i = 0; i < deg; i += 4) {
            int i1 = min(i + 1, deg - 1), i2 = min(i + 2, deg - 1), i3 = min(i + 3, deg - 1);
            int2 e0 = __ldg(&ce[i]);
            int2 e1 = __ldg(&ce[i1]);
            int2 e2 = __ldg(&ce[i2]);
            int2 e3 = __ldg(&ce[i3]);
            float w0 = __int_as_float(e0.y);
            float w1 = (i + 1 < deg) ? __int_as_float(e1.y) : 0.f;
            float w2 = (i + 2 < deg) ? __int_as_float(e2.y) : 0.f;
            float w3 = (i + 3 < deg) ? __int_as_float(e3.y) : 0.f;
            float2 v0 = __bfloat1622float2(((const __nv_bfloat162*)(g_x16 + (size_t)e0.x * IN_DIM))[lane]);
            float2 v1 = __bfloat1622float2(((const __nv_bfloat162*)(g_x16 + (size_t)e1.x * IN_DIM))[lane]);
            float2 v2 = __bfloat1622float2(((const __nv_bfloat162*)(g_x16 + (size_t)e2.x * IN_DIM))[lane]);
            float2 v3 = __bfloat1622float2(((const __nv_bfloat162*)(g_x16 + (size_t)e3.x * IN_DIM))[lane]);
            a0 += w0 * v0.x + w1 * v1.x + w2 * v2.x + w3 * v3.x;
            a1 += w0 * v0.y + w1 * v1.y + w2 * v2.y + w3 * v3.y;
        }
        float rd = rsqrtf((float)max(degf, 1));
        ((__nv_bfloat162*)&g_agg1[(size_t)v * IN_DIM])[lane] =
            __floats2bfloat162_rn(a0 * rd, a1 * rd);
    }
}

// layer-2 gather from fp16 h1 (pre-scaled by rs_src); lane = 4 features
__global__ __launch_bounds__(256) void k_agg2() {
    int tid = threadIdx.x, w = tid >> 5, lane = tid & 31;
    int vb = blockIdx.x * 32 + w * 4;
    #pragma unroll
    for (int nn = 0; nn < 4; nn++) {
        int v = vb + nn;
        int degf = g_cursor[v];
        int deg  = min(degf, CAP);
        const int2* ce = &g_csre[(size_t)v * CAP];
        float a0 = 0.f, a1 = 0.f, a2 = 0.f, a3 = 0.f;
        for (int i = 0; i < deg; i += 4) {
            int i1 = min(i + 1, deg - 1), i2 = min(i + 2, deg - 1), i3 = min(i + 3, deg - 1);
            int2 e0 = __ldg(&ce[i]);
            int2 e1 = __ldg(&ce[i1]);
            int2 e2 = __ldg(&ce[i2]);
            int2 e3 = __ldg(&ce[i3]);
            float w0 = __int_as_float(e0.y);
            float w1 = (i + 1 < deg) ? __int_as_float(e1.y) : 0.f;
            float w2 = (i + 2 < deg) ? __int_as_float(e2.y) : 0.f;
            float w3 = (i + 3 < deg) ? __int_as_float(e3.y) : 0.f;
            uint2 u0 = ((const uint2*)(g_h1h + (size_t)e0.x * HID))[lane];
            uint2 u1 = ((const uint2*)(g_h1h + (size_t)e1.x * HID))[lane];
            uint2 u2 = ((const uint2*)(g_h1h + (size_t)e2.x * HID))[lane];
            uint2 u3 = ((const uint2*)(g_h1h + (size_t)e3.x * HID))[lane];
            float2 p, q;
            p = __half22float2(*(const __half2*)&u0.x); q = __half22float2(*(const __half2*)&u0.y);
            a0 += w0 * p.x; a1 += w0 * p.y; a2 += w0 * q.x; a3 += w0 * q.y;
            p = __half22float2(*(const __half2*)&u1.x); q = __half22float2(*(const __half2*)&u1.y);
            a0 += w1 * p.x; a1 += w1 * p.y; a2 += w1 * q.x; a3 += w1 * q.y;
            p = __half22float2(*(const __half2*)&u2.x); q = __half22float2(*(const __half2*)&u2.y);
            a0 += w2 * p.x; a1 += w2 * p.y; a2 += w2 * q.x; a3 += w2 * q.y;
            p = __half22float2(*(const __half2*)&u3.x); q = __half22float2(*(const __half2*)&u3.y);
            a0 += w3 * p.x; a1 += w3 * p.y; a2 += w3 * q.x; a3 += w3 * q.y;
        }
        float rd = rsqrtf((float)max(degf, 1));
        __nv_bfloat162 b0 = __floats2bfloat162_rn(a0 * rd, a1 * rd);
        __nv_bfloat162 b1 = __floats2bfloat162_rn(a2 * rd, a3 * rd);
        uint2 packed;
        packed.x = *(uint32_t*)&b0;
        packed.y = *(uint32_t*)&b1;
        ((uint2*)&g_agg2[(size_t)v * HID])[lane] = packed;
    }
}

// ---------------- WMMA GEMM + fused GraphNorm stats --------------------------
__global__ __launch_bounds__(256) void k_gemm(int layer) {
    extern __shared__ __nv_bfloat16 smb[];
    const int K   = (layer == 1) ? IN_DIM : HID;
    const int pitch = K + 8;
    __nv_bfloat16* sA = smb;                       // [128][pitch]
    __nv_bfloat16* sB = smb + 128 * pitch;         // [128][pitch]
    const __nv_bfloat16* Ag = (layer == 1) ? g_agg1 : g_agg2;
    const __nv_bfloat16* Bg = (layer == 1) ? g_w1t  : g_w2t;
    int tid = threadIdx.x;
    size_t m0 = (size_t)blockIdx.x * 128;

    int vecs = K / 8;                              // uint4 = 8 bf16
    for (int i = tid; i < 128 * vecs; i += 256) {
        int r = i / vecs, c = i % vecs;
        *(uint4*)&sA[r * pitch + c * 8] = *(const uint4*)&Ag[(m0 + r) * K + c * 8];
        *(uint4*)&sB[r * pitch + c * 8] = *(const uint4*)&Bg[(size_t)r * K + c * 8];
    }
    __syncthreads();

    int w = tid >> 5;
    wmma::fragment<wmma::accumulator, 16, 16, 16, float> acc[8];
    #pragma unroll
    for (int n = 0; n < 8; n++) wmma::fill_fragment(acc[n], 0.f);

    for (int k = 0; k < K; k += 16) {
        wmma::fragment<wmma::matrix_a, 16, 16, 16, __nv_bfloat16, wmma::row_major> fa;
        wmma::load_matrix_sync(fa, &sA[(w * 16) * pitch + k], pitch);
        #pragma unroll
        for (int n = 0; n < 8; n++) {
            wmma::fragment<wmma::matrix_b, 16, 16, 16, __nv_bfloat16, wmma::col_major> fb;
            wmma::load_matrix_sync(fb, &sB[(n * 16) * pitch + k], pitch);
            wmma::mma_sync(acc[n], fa, fb, acc[n]);
        }
    }

    // ---- epilogue: stage to smem, fused stats, coalesced global write ----
    __syncthreads();
    float* Hs = (float*)smb;                       // [128][128] = 64 KB
    #pragma unroll
    for (int n = 0; n < 8; n++)
        wmma::store_matrix_sync(&Hs[(w * 16) * HID + n * 16], acc[n], HID,
                                wmma::mem_row_major);
    __syncthreads();

    float* H  = (layer == 1) ? g_h1pre : g_h2pre;
    float* st = (layer == 1) ? g_stats1 : g_stats2;

    int col = tid & 127, half = tid >> 7;
    float s = 0.f, ss = 0.f;
    #pragma unroll 8
    for (int r = 0; r < 64; r++) {
        float vv = Hs[(half * 64 + r) * HID + col];
        s += vv;
        ss += vv * vv;
    }
    atomicAdd(&st[col], s);
    atomicAdd(&st[HID + col], ss);

    for (int i = tid; i < 128 * 32; i += 256) {
        int r = i >> 5, c = i & 31;
        ((float4*)&H[(m0 + r) * HID])[c] = ((const float4*)&Hs[r * HID])[c];
    }
}

// ---------------- norm / readout ---------------------------------------------

__global__ void k_norm(int layer,
                       const float* __restrict__ gamma, const float* __restrict__ beta,
                       const float* __restrict__ alpha) {
    __shared__ float sRs[128];
    int j = threadIdx.x;
    int b = blockIdx.x;
    const float* stats = (layer == 1) ? g_stats1 : g_stats2;
    const float* hpre  = (layer == 1) ? g_h1pre : g_h2pre;
    int rcol   = (layer == 1) ? 0 : HID;
    int writeH = (layer == 1) ? 1 : 0;

    if (writeH) sRs[j] = g_rs_src[b * 128 + j];
    __syncthreads();

    const float invN = 1.0f / (float)N_NODES;
    float mu  = stats[j] * invN;
    float ex2 = stats[HID + j] * invN;
    float al  = alpha[j];
    float var = ex2 + mu * mu * (al * al - 2.f * al);
    float istd = rsqrtf(var + EPSV);
    float ga = gamma[j] * istd;
    float be = beta[j];
    float amu = al * mu;

    int g = (b * 128) / P_NODES;
    const float* in = &hpre[(size_t)b * 128 * HID];
    __half* out = &g_h1h[(size_t)b * 128 * HID];
    float rsum = 0.f;
    #pragma unroll 4
    for (int r = 0; r < 128; r++) {
        float v = in[r * HID + j];
        float c = (v - amu) * ga + be;
        float y = c > 0.f ? c : SLOPE * c;
        if (writeH) out[r * HID + j] = __float2half(y * sRs[r]);
        rsum += y;
    }
    atomicAdd(&g_r[g * (2 * HID) + rcol + j], rsum);
}

__global__ void k_final(const float* __restrict__ Wc, float* __restrict__ out) {
    int t = threadIdx.x;
    int b = t >> 4, o = t & 15;
    const float* rb = &g_r[b * 2 * HID];
    const float* wr = &Wc[o * 2 * HID];
    float s = 0.f;
    #pragma unroll 8
    for (int k = 0; k < 2 * HID; k++) s += rb[k] * wr[k];
    out[b * OUT_DIM + o] = s * (1.0f / (float)P_NODES);
}

// ---------------- launch -----------------------------------------------------

extern "C" void kernel_launch(void* const* d_in, const int* in_sizes, int n_in,
                              void* d_out, int out_size) {
    const float* features = (const float*)d_in[0];
    const float* ew       = (const float*)d_in[1];
    const int*   src      = (const int*)d_in[2];
    const int*   dst      = (const int*)d_in[3];
    const float* W1       = (const float*)d_in[4];
    const float* W2       = (const float*)d_in[5];
    const float* Wc       = (const float*)d_in[6];
    const float* gamma1   = (const float*)d_in[7];
    const float* beta1    = (const float*)d_in[8];
    const float* alpha1   = (const float*)d_in[9];
    const float* gamma2   = (const float*)d_in[10];
    const float* beta2    = (const float*)d_in[11];
    const float* alpha2   = (const float*)d_in[12];
    float* out = (float*)d_out;

    const int smem1 = 128 * 128 * 4;                               // 65536
    const int smem2 = 2 * 128 * (HID + 8) * 2;                     // 69632
    cudaFuncSetAttribute(k_gemm, cudaFuncAttributeMaxDynamicSharedMemorySize, smem2);

    k_zero<<<N_NODES / 256, 256>>>();
    k_build<<<E_EDGES / 1024, 256>>>(src, dst, ew);
    k_rs<<<N_NODES / 256, 256>>>();
    k_prep<<<4097, 256>>>(features, W1, W2);

    k_agg1<<<N_NODES / 32, 256>>>();
    k_gemm<<<N_NODES / 128, 256, smem1>>>(1);
    k_norm<<<1024, 128>>>(1, gamma1, beta1, alpha1);

    k_agg2<<<N_NODES / 32, 256>>>();
    k_gemm<<<N_NODES / 128, 256, smem2>>>(2);
    k_norm<<<1024, 128>>>(2, gamma2, beta2, alpha2);

    k_final<<<1, 512>>>(Wc, out);
}

// round 11
// speedup vs baseline: 1.1698x; 1.0826x over previous
#include <cuda_runtime.h>
#include <cuda_fp16.h>
#include <cuda_bf16.h>
#include <mma.h>
#include <cstdint>

using namespace nvcuda;

#define N_NODES 131072
#define P_NODES 4096
#define B_GR    32
#define E_EDGES 2097152
#define IN_DIM  64
#define HID     128
#define OUT_DIM 16
#define CAP     64
#define EPSV    1e-5f
#define SLOPE   0.01f

// ---------------- scratch (device globals; no allocations allowed) ----------
__device__ int    g_deg_src[N_NODES];
__device__ int    g_cursor[N_NODES];                 // dst degree after build
__device__ float  g_rs_src[N_NODES];
__device__ int2   g_csre[(size_t)N_NODES * CAP];     // packed {src, raw ew}
__device__ __nv_bfloat16 g_x16[(size_t)N_NODES * IN_DIM];   // bf16 features * rs_src
__device__ __nv_bfloat16 g_agg1[(size_t)N_NODES * IN_DIM];
__device__ __nv_bfloat16 g_agg2[(size_t)N_NODES * HID];
__device__ __nv_bfloat16 g_w1t[HID * IN_DIM];        // W1^T  [n][k]
__device__ __nv_bfloat16 g_w2t[HID * HID];           // W2^T  [n][k]
__device__ float  g_h1pre[(size_t)N_NODES * HID];
__device__ __half g_h1h[(size_t)N_NODES * HID];      // normalized h1 * rs_src (fp16)
__device__ float  g_h2pre[(size_t)N_NODES * HID];
__device__ float  g_stats1[2 * HID];
__device__ float  g_stats2[2 * HID];
__device__ float  g_r[B_GR * 2 * HID];

// ---------------- setup -----------------------------------------------------

__global__ void k_zero() {
    int i = blockIdx.x * blockDim.x + threadIdx.x;
    if (i < N_NODES) { g_deg_src[i] = 0; g_cursor[i] = 0; }
    if (i < 2 * HID) { g_stats1[i] = 0.f; g_stats2[i] = 0.f; }
    if (i < B_GR * 2 * HID) { g_r[i] = 0.f; }
}

// 4 edges/thread: vector loads + independent atomic chains; writes packed CSR.
__global__ __launch_bounds__(256) void k_build(const int* __restrict__ src,
                                               const int* __restrict__ dst,
                                               const float* __restrict__ ew) {
    int e4 = (blockIdx.x * 256 + threadIdx.x) * 4;
    int4   s4 = *(const int4*)&src[e4];
    int4   d4 = *(const int4*)&dst[e4];
    float4 w4 = *(const float4*)&ew[e4];
    int p0 = atomicAdd(&g_cursor[d4.x], 1);
    int p1 = atomicAdd(&g_cursor[d4.y], 1);
    int p2 = atomicAdd(&g_cursor[d4.z], 1);
    int p3 = atomicAdd(&g_cursor[d4.w], 1);
    atomicAdd(&g_deg_src[s4.x], 1);
    atomicAdd(&g_deg_src[s4.y], 1);
    atomicAdd(&g_deg_src[s4.z], 1);
    atomicAdd(&g_deg_src[s4.w], 1);
    if (p0 < CAP) g_csre[(size_t)d4.x * CAP + p0] = make_int2(s4.x, __float_as_int(w4.x));
    if (p1 < CAP) g_csre[(size_t)d4.y * CAP + p1] = make_int2(s4.y, __float_as_int(w4.y));
    if (p2 < CAP) g_csre[(size_t)d4.z * CAP + p2] = make_int2(s4.z, __float_as_int(w4.z));
    if (p3 < CAP) g_csre[(size_t)d4.w * CAP + p3] = make_int2(s4.w, __float_as_int(w4.w));
}

__global__ void k_rs() {
    int v = blockIdx.x * blockDim.x + threadIdx.x;
    if (v < N_NODES) g_rs_src[v] = rsqrtf((float)max(g_deg_src[v], 1));
}

// blocks [0,2048): features -> bf16 * rs_src; 16 floats/thread via 4 indep chains.
// block 2048: transpose W1,W2 to bf16 K-major.
__global__ __launch_bounds__(256) void k_prep(const float* __restrict__ x,
                                              const float* __restrict__ W1,
                                              const float* __restrict__ W2) {
    int b = blockIdx.x, t = threadIdx.x;
    if (b < 2048) {
        int i0 = b * 4096 + t * 16;                 // 16 floats, within one row
        int row = i0 >> 6;
        float rs = g_rs_src[row];
        float4 a0 = *(const float4*)&x[i0];
        float4 a1 = *(const float4*)&x[i0 + 4];
        float4 a2 = *(const float4*)&x[i0 + 8];
        float4 a3 = *(const float4*)&x[i0 + 12];
        uint4 o0, o1;
        __nv_bfloat162 c0 = __floats2bfloat162_rn(a0.x * rs, a0.y * rs);
        __nv_bfloat162 c1 = __floats2bfloat162_rn(a0.z * rs, a0.w * rs);
        __nv_bfloat162 c2 = __floats2bfloat162_rn(a1.x * rs, a1.y * rs);
        __nv_bfloat162 c3 = __floats2bfloat162_rn(a1.z * rs, a1.w * rs);
        __nv_bfloat162 c4 = __floats2bfloat162_rn(a2.x * rs, a2.y * rs);
        __nv_bfloat162 c5 = __floats2bfloat162_rn(a2.z * rs, a2.w * rs);
        __nv_bfloat162 c6 = __floats2bfloat162_rn(a3.x * rs, a3.y * rs);
        __nv_bfloat162 c7 = __floats2bfloat162_rn(a3.z * rs, a3.w * rs);
        o0.x = *(uint32_t*)&c0; o0.y = *(uint32_t*)&c1;
        o0.z = *(uint32_t*)&c2; o0.w = *(uint32_t*)&c3;
        o1.x = *(uint32_t*)&c4; o1.y = *(uint32_t*)&c5;
        o1.z = *(uint32_t*)&c6; o1.w = *(uint32_t*)&c7;
        *(uint4*)&g_x16[i0]     = o0;
        *(uint4*)&g_x16[i0 + 8] = o1;
    } else {
        for (int i = t; i < HID * IN_DIM; i += 256) {
            int n = i / IN_DIM, k = i % IN_DIM;
            g_w1t[i] = __float2bfloat16(W1[k * HID + n]);
        }
        for (int i = t; i < HID * HID; i += 256) {
            int n = i / HID, k = i % HID;
            g_w2t[i] = __float2bfloat16(W2[k * HID + n]);
        }
    }
}

// ---------------- aggregation (pure gather; weight = raw ew; MLP=8) ----------
__global__ __launch_bounds__(256) void k_agg1() {
    int tid = threadIdx.x, w = tid >> 5, lane = tid & 31;
    int vb = blockIdx.x * 32 + w * 4;
    #pragma unroll
    for (int nn = 0; nn < 4; nn++) {
        int v = vb + nn;
        int degf = g_cursor[v];
        int deg  = min(degf, CAP);
        const int2* ce = &g_csre[(size_t)v * CAP];
        float a0 = 0.f, a1 = 0.f;
        for (int i = 0; i < deg; i += 8) {
            int   idx[8];
            float wt[8];
            #pragma unroll
            for (int u = 0; u < 8; u++) {
                int j = min(i + u, deg - 1);
                int2 e = __ldg(&ce[j]);
                idx[u] = e.x;
                wt[u]  = (i + u < deg) ? __int_as_float(e.y) : 0.f;
            }
            float2 vv[8];
            #pragma unroll
            for (int u = 0; u < 8; u++)
                vv[u] = __bfloat1622float2(((const __nv_bfloat162*)(g_x16 + (size_t)idx[u] * IN_DIM))[lane]);
            #pragma unroll
            for (int u = 0; u < 8; u++) {
                a0 += wt[u] * vv[u].x;
                a1 += wt[u] * vv[u].y;
            }
        }
        float rd = rsqrtf((float)max(degf, 1));
        ((__nv_bfloat162*)&g_agg1[(size_t)v * IN_DIM])[lane] =
            __floats2bfloat162_rn(a0 * rd, a1 * rd);
    }
}

__global__ __launch_bounds__(256) void k_agg2() {
    int tid = threadIdx.x, w = tid >> 5, lane = tid & 31;
    int vb = blockIdx.x * 32 + w * 4;
    #pragma unroll
    for (int nn = 0; nn < 4; nn++) {
        int v = vb + nn;
        int degf = g_cursor[v];
        int deg  = min(degf, CAP);
        const int2* ce = &g_csre[(size_t)v * CAP];
        float a0 = 0.f, a1 = 0.f, a2 = 0.f, a3 = 0.f;
        for (int i = 0; i < deg; i += 8) {
            int   idx[8];
            float wt[8];
            #pragma unroll
            for (int u = 0; u < 8; u++) {
                int j = min(i + u, deg - 1);
                int2 e = __ldg(&ce[j]);
                idx[u] = e.x;
                wt[u]  = (i + u < deg) ? __int_as_float(e.y) : 0.f;
            }
            uint2 uu[8];
            #pragma unroll
            for (int u = 0; u < 8; u++)
                uu[u] = ((const uint2*)(g_h1h + (size_t)idx[u] * HID))[lane];
            #pragma unroll
            for (int u = 0; u < 8; u++) {
                float2 p = __half22float2(*(const __half2*)&uu[u].x);
                float2 q = __half22float2(*(const __half2*)&uu[u].y);
                a0 += wt[u] * p.x; a1 += wt[u] * p.y;
                a2 += wt[u] * q.x; a3 += wt[u] * q.y;
            }
        }
        float rd = rsqrtf((float)max(degf, 1));
        __nv_bfloat162 b0 = __floats2bfloat162_rn(a0 * rd, a1 * rd);
        __nv_bfloat162 b1 = __floats2bfloat162_rn(a2 * rd, a3 * rd);
        uint2 packed;
        packed.x = *(uint32_t*)&b0;
        packed.y = *(uint32_t*)&b1;
        ((uint2*)&g_agg2[(size_t)v * HID])[lane] = packed;
    }
}

// ---------------- WMMA GEMM + fused GraphNorm stats --------------------------
__global__ __launch_bounds__(256) void k_gemm(int layer) {
    extern __shared__ __nv_bfloat16 smb[];
    const int K   = (layer == 1) ? IN_DIM : HID;
    const int pitch = K + 8;
    __nv_bfloat16* sA = smb;                       // [128][pitch]
    __nv_bfloat16* sB = smb + 128 * pitch;         // [128][pitch]
    const __nv_bfloat16* Ag = (layer == 1) ? g_agg1 : g_agg2;
    const __nv_bfloat16* Bg = (layer == 1) ? g_w1t  : g_w2t;
    int tid = threadIdx.x;
    size_t m0 = (size_t)blockIdx.x * 128;

    int vecs = K / 8;                              // uint4 = 8 bf16
    for (int i = tid; i < 128 * vecs; i += 256) {
        int r = i / vecs, c = i % vecs;
        *(uint4*)&sA[r * pitch + c * 8] = *(const uint4*)&Ag[(m0 + r) * K + c * 8];
        *(uint4*)&sB[r * pitch + c * 8] = *(const uint4*)&Bg[(size_t)r * K + c * 8];
    }
    __syncthreads();

    int w = tid >> 5;
    wmma::fragment<wmma::accumulator, 16, 16, 16, float> acc[8];
    #pragma unroll
    for (int n = 0; n < 8; n++) wmma::fill_fragment(acc[n], 0.f);

    for (int k = 0; k < K; k += 16) {
        wmma::fragment<wmma::matrix_a, 16, 16, 16, __nv_bfloat16, wmma::row_major> fa;
        wmma::load_matrix_sync(fa, &sA[(w * 16) * pitch + k], pitch);
        #pragma unroll
        for (int n = 0; n < 8; n++) {
            wmma::fragment<wmma::matrix_b, 16, 16, 16, __nv_bfloat16, wmma::col_major> fb;
            wmma::load_matrix_sync(fb, &sB[(n * 16) * pitch + k], pitch);
            wmma::mma_sync(acc[n], fa, fb, acc[n]);
        }
    }

    // ---- epilogue: stage to smem, fused stats, coalesced global write ----
    __syncthreads();
    float* Hs = (float*)smb;                       // [128][128] = 64 KB
    #pragma unroll
    for (int n = 0; n < 8; n++)
        wmma::store_matrix_sync(&Hs[(w * 16) * HID + n * 16], acc[n], HID,
                                wmma::mem_row_major);
    __syncthreads();

    float* H  = (layer == 1) ? g_h1pre : g_h2pre;
    float* st = (layer == 1) ? g_stats1 : g_stats2;

    int col = tid & 127, half = tid >> 7;
    float s = 0.f, ss = 0.f;
    #pragma unroll 8
    for (int r = 0; r < 64; r++) {
        float vv = Hs[(half * 64 + r) * HID + col];
        s += vv;
        ss += vv * vv;
    }
    atomicAdd(&st[col], s);
    atomicAdd(&st[HID + col], ss);

    for (int i = tid; i < 128 * 32; i += 256) {
        int r = i >> 5, c = i & 31;
        ((float4*)&H[(m0 + r) * HID])[c] = ((const float4*)&Hs[r * HID])[c];
    }
}

// ---------------- norm / readout ---------------------------------------------
// 2048 blocks x 64 rows (doubled concurrency vs 1024x128).
__global__ void k_norm(int layer,
                       const float* __restrict__ gamma, const float* __restrict__ beta,
                       const float* __restrict__ alpha) {
    __shared__ float sRs[64];
    int j = threadIdx.x;
    int b = blockIdx.x;
    const float* stats = (layer == 1) ? g_stats1 : g_stats2;
    const float* hpre  = (layer == 1) ? g_h1pre : g_h2pre;
    int rcol   = (layer == 1) ? 0 : HID;
    int writeH = (layer == 1) ? 1 : 0;

    if (writeH && j < 64) sRs[j] = g_rs_src[b * 64 + j];
    __syncthreads();

    const float invN = 1.0f / (float)N_NODES;
    float mu  = stats[j] * invN;
    float ex2 = stats[HID + j] * invN;
    float al  = alpha[j];
    float var = ex2 + mu * mu * (al * al - 2.f * al);
    float istd = rsqrtf(var + EPSV);
    float ga = gamma[j] * istd;
    float be = beta[j];
    float amu = al * mu;

    int g = (b * 64) / P_NODES;
    const float* in = &hpre[(size_t)b * 64 * HID];
    __half* out = &g_h1h[(size_t)b * 64 * HID];
    float rsum = 0.f;
    #pragma unroll 4
    for (int r = 0; r < 64; r++) {
        float v = in[r * HID + j];
        float c = (v - amu) * ga + be;
        float y = c > 0.f ? c : SLOPE * c;
        if (writeH) out[r * HID + j] = __float2half(y * sRs[r]);
        rsum += y;
    }
    atomicAdd(&g_r[g * (2 * HID) + rcol + j], rsum);
}

__global__ void k_final(const float* __restrict__ Wc, float* __restrict__ out) {
    int t = threadIdx.x;
    int b = t >> 4, o = t & 15;
    const float* rb = &g_r[b * 2 * HID];
    const float* wr = &Wc[o * 2 * HID];
    float s = 0.f;
    #pragma unroll 8
    for (int k = 0; k < 2 * HID; k++) s += rb[k] * wr[k];
    out[b * OUT_DIM + o] = s * (1.0f / (float)P_NODES);
}

// ---------------- launch -----------------------------------------------------

extern "C" void kernel_launch(void* const* d_in, const int* in_sizes, int n_in,
                              void* d_out, int out_size) {
    const float* features = (const float*)d_in[0];
    const float* ew       = (const float*)d_in[1];
    const int*   src      = (const int*)d_in[2];
    const int*   dst      = (const int*)d_in[3];
    const float* W1       = (const float*)d_in[4];
    const float* W2       = (const float*)d_in[5];
    const float* Wc       = (const float*)d_in[6];
    const float* gamma1   = (const float*)d_in[7];
    const float* beta1    = (const float*)d_in[8];
    const float* alpha1   = (const float*)d_in[9];
    const float* gamma2   = (const float*)d_in[10];
    const float* beta2    = (const float*)d_in[11];
    const float* alpha2   = (const float*)d_in[12];
    float* out = (float*)d_out;

    const int smem1 = 128 * 128 * 4;                               // 65536
    const int smem2 = 2 * 128 * (HID + 8) * 2;                     // 69632
    cudaFuncSetAttribute(k_gemm, cudaFuncAttributeMaxDynamicSharedMemorySize, smem2);

    k_zero<<<N_NODES / 256, 256>>>();
    k_build<<<E_EDGES / 1024, 256>>>(src, dst, ew);
    k_rs<<<N_NODES / 256, 256>>>();
    k_prep<<<2049, 256>>>(features, W1, W2);

    k_agg1<<<N_NODES / 32, 256>>>();
    k_gemm<<<N_NODES / 128, 256, smem1>>>(1);
    k_norm<<<2048, 128>>>(1, gamma1, beta1, alpha1);

    k_agg2<<<N_NODES / 32, 256>>>();
    k_gemm<<<N_NODES / 128, 256, smem2>>>(2);
    k_norm<<<2048, 128>>>(2, gamma2, beta2, alpha2);

    k_final<<<1, 512>>>(Wc, out);
}

// round 12
// speedup vs baseline: 1.2180x; 1.0412x over previous
#include <cuda_runtime.h>
#include <cuda_fp16.h>
#include <cuda_bf16.h>
#include <mma.h>
#include <cstdint>

using namespace nvcuda;

#define N_NODES 131072
#define P_NODES 4096
#define B_GR    32
#define E_EDGES 2097152
#define IN_DIM  64
#define HID     128
#define OUT_DIM 16
#define CAP     64
#define EPSV    1e-5f
#define SLOPE   0.01f

// ---------------- scratch (device globals; no allocations allowed) ----------
__device__ int    g_deg_src[N_NODES];
__device__ int    g_cursor[N_NODES];                 // dst degree after build
__device__ float  g_rs_src[N_NODES];
__device__ int2   g_csre[(size_t)N_NODES * CAP];     // packed {src, raw ew}
__device__ __nv_bfloat16 g_x16[(size_t)N_NODES * IN_DIM];   // bf16 features * rs_src
__device__ __nv_bfloat16 g_agg1[(size_t)N_NODES * IN_DIM];
__device__ __nv_bfloat16 g_agg2[(size_t)N_NODES * HID];
__device__ __nv_bfloat16 g_w1t[HID * IN_DIM];        // W1^T  [n][k]
__device__ __nv_bfloat16 g_w2t[HID * HID];           // W2^T  [n][k]
__device__ __half g_h1pre[(size_t)N_NODES * HID];    // pre-norm h1 (fp16)
__device__ __half g_h1h[(size_t)N_NODES * HID];      // normalized h1 * rs_src (fp16)
__device__ __half g_h2pre[(size_t)N_NODES * HID];    // pre-norm h2 (fp16)
__device__ float  g_stats1[2 * HID];
__device__ float  g_stats2[2 * HID];
__device__ float  g_r[B_GR * 2 * HID];

// ---------------- setup -----------------------------------------------------

__global__ void k_zero() {
    int i = blockIdx.x * blockDim.x + threadIdx.x;
    if (i < N_NODES) { g_deg_src[i] = 0; g_cursor[i] = 0; }
    if (i < 2 * HID) { g_stats1[i] = 0.f; g_stats2[i] = 0.f; }
    if (i < B_GR * 2 * HID) { g_r[i] = 0.f; }
}

// 4 edges/thread: vector loads + independent atomic chains; writes packed CSR.
__global__ __launch_bounds__(256) void k_build(const int* __restrict__ src,
                                               const int* __restrict__ dst,
                                               const float* __restrict__ ew) {
    int e4 = (blockIdx.x * 256 + threadIdx.x) * 4;
    int4   s4 = *(const int4*)&src[e4];
    int4   d4 = *(const int4*)&dst[e4];
    float4 w4 = *(const float4*)&ew[e4];
    int p0 = atomicAdd(&g_cursor[d4.x], 1);
    int p1 = atomicAdd(&g_cursor[d4.y], 1);
    int p2 = atomicAdd(&g_cursor[d4.z], 1);
    int p3 = atomicAdd(&g_cursor[d4.w], 1);
    atomicAdd(&g_deg_src[s4.x], 1);
    atomicAdd(&g_deg_src[s4.y], 1);
    atomicAdd(&g_deg_src[s4.z], 1);
    atomicAdd(&g_deg_src[s4.w], 1);
    if (p0 < CAP) g_csre[(size_t)d4.x * CAP + p0] = make_int2(s4.x, __float_as_int(w4.x));
    if (p1 < CAP) g_csre[(size_t)d4.y * CAP + p1] = make_int2(s4.y, __float_as_int(w4.y));
    if (p2 < CAP) g_csre[(size_t)d4.z * CAP + p2] = make_int2(s4.z, __float_as_int(w4.z));
    if (p3 < CAP) g_csre[(size_t)d4.w * CAP + p3] = make_int2(s4.w, __float_as_int(w4.w));
}

__global__ void k_rs() {
    int v = blockIdx.x * blockDim.x + threadIdx.x;
    if (v < N_NODES) g_rs_src[v] = rsqrtf((float)max(g_deg_src[v], 1));
}

// blocks [0,1024): features -> bf16 * rs_src; 32 floats/thread (8 indep float4).
// block 1024: transpose W1,W2 to bf16 K-major.
__global__ __launch_bounds__(256) void k_prep(const float* __restrict__ x,
                                              const float* __restrict__ W1,
                                              const float* __restrict__ W2) {
    int b = blockIdx.x, t = threadIdx.x;
    if (b < 1024) {
        int i0 = b * 8192 + t * 32;                 // 32 floats, within one row half
        int row = i0 >> 6;
        float rs = g_rs_src[row];
        float4 a[8];
        #pragma unroll
        for (int u = 0; u < 8; u++) a[u] = *(const float4*)&x[i0 + 4 * u];
        #pragma unroll
        for (int u = 0; u < 4; u++) {
            uint4 o;
            __nv_bfloat162 c0 = __floats2bfloat162_rn(a[2*u].x * rs, a[2*u].y * rs);
            __nv_bfloat162 c1 = __floats2bfloat162_rn(a[2*u].z * rs, a[2*u].w * rs);
            __nv_bfloat162 c2 = __floats2bfloat162_rn(a[2*u+1].x * rs, a[2*u+1].y * rs);
            __nv_bfloat162 c3 = __floats2bfloat162_rn(a[2*u+1].z * rs, a[2*u+1].w * rs);
            o.x = *(uint32_t*)&c0; o.y = *(uint32_t*)&c1;
            o.z = *(uint32_t*)&c2; o.w = *(uint32_t*)&c3;
            *(uint4*)&g_x16[i0 + 8 * u] = o;
        }
    } else {
        for (int i = t; i < HID * IN_DIM; i += 256) {
            int n = i / IN_DIM, k = i % IN_DIM;
            g_w1t[i] = __float2bfloat16(W1[k * HID + n]);
        }
        for (int i = t; i < HID * HID; i += 256) {
            int n = i / HID, k = i % HID;
            g_w2t[i] = __float2bfloat16(W2[k * HID + n]);
        }
    }
}

// ---------------- aggregation (pure gather; weight = raw ew; MLP=8) ----------
__global__ __launch_bounds__(256) void k_agg1() {
    int tid = threadIdx.x, w = tid >> 5, lane = tid & 31;
    int vb = blockIdx.x * 32 + w * 4;
    #pragma unroll
    for (int nn = 0; nn < 4; nn++) {
        int v = vb + nn;
        int degf = g_cursor[v];
        int deg  = min(degf, CAP);
        const int2* ce = &g_csre[(size_t)v * CAP];
        float a0 = 0.f, a1 = 0.f;
        for (int i = 0; i < deg; i += 8) {
            int   idx[8];
            float wt[8];
            #pragma unroll
            for (int u = 0; u < 8; u++) {
                int j = min(i + u, deg - 1);
                int2 e = __ldg(&ce[j]);
                idx[u] = e.x;
                wt[u]  = (i + u < deg) ? __int_as_float(e.y) : 0.f;
            }
            float2 vv[8];
            #pragma unroll
            for (int u = 0; u < 8; u++)
                vv[u] = __bfloat1622float2(((const __nv_bfloat162*)(g_x16 + (size_t)idx[u] * IN_DIM))[lane]);
            #pragma unroll
            for (int u = 0; u < 8; u++) {
                a0 += wt[u] * vv[u].x;
                a1 += wt[u] * vv[u].y;
            }
        }
        float rd = rsqrtf((float)max(degf, 1));
        ((__nv_bfloat162*)&g_agg1[(size_t)v * IN_DIM])[lane] =
            __floats2bfloat162_rn(a0 * rd, a1 * rd);
    }
}

__global__ __launch_bounds__(256) void k_agg2() {
    int tid = threadIdx.x, w = tid >> 5, lane = tid & 31;
    int vb = blockIdx.x * 32 + w * 4;
    #pragma unroll
    for (int nn = 0; nn < 4; nn++) {
        int v = vb + nn;
        int degf = g_cursor[v];
        int deg  = min(degf, CAP);
        const int2* ce = &g_csre[(size_t)v * CAP];
        float a0 = 0.f, a1 = 0.f, a2 = 0.f, a3 = 0.f;
        for (int i = 0; i < deg; i += 8) {
            int   idx[8];
            float wt[8];
            #pragma unroll
            for (int u = 0; u < 8; u++) {
                int j = min(i + u, deg - 1);
                int2 e = __ldg(&ce[j]);
                idx[u] = e.x;
                wt[u]  = (i + u < deg) ? __int_as_float(e.y) : 0.f;
            }
            uint2 uu[8];
            #pragma unroll
            for (int u = 0; u < 8; u++)
                uu[u] = ((const uint2*)(g_h1h + (size_t)idx[u] * HID))[lane];
            #pragma unroll
            for (int u = 0; u < 8; u++) {
                float2 p = __half22float2(*(const __half2*)&uu[u].x);
                float2 q = __half22float2(*(const __half2*)&uu[u].y);
                a0 += wt[u] * p.x; a1 += wt[u] * p.y;
                a2 += wt[u] * q.x; a3 += wt[u] * q.y;
            }
        }
        float rd = rsqrtf((float)max(degf, 1));
        __nv_bfloat162 b0 = __floats2bfloat162_rn(a0 * rd, a1 * rd);
        __nv_bfloat162 b1 = __floats2bfloat162_rn(a2 * rd, a3 * rd);
        uint2 packed;
        packed.x = *(uint32_t*)&b0;
        packed.y = *(uint32_t*)&b1;
        ((uint2*)&g_agg2[(size_t)v * HID])[lane] = packed;
    }
}

// ---------------- WMMA GEMM + fused GraphNorm stats --------------------------
__global__ __launch_bounds__(256) void k_gemm(int layer) {
    extern __shared__ __nv_bfloat16 smb[];
    const int K   = (layer == 1) ? IN_DIM : HID;
    const int pitch = K + 8;
    __nv_bfloat16* sA = smb;                       // [128][pitch]
    __nv_bfloat16* sB = smb + 128 * pitch;         // [128][pitch]
    const __nv_bfloat16* Ag = (layer == 1) ? g_agg1 : g_agg2;
    const __nv_bfloat16* Bg = (layer == 1) ? g_w1t  : g_w2t;
    int tid = threadIdx.x;
    size_t m0 = (size_t)blockIdx.x * 128;

    int vecs = K / 8;                              // uint4 = 8 bf16
    for (int i = tid; i < 128 * vecs; i += 256) {
        int r = i / vecs, c = i % vecs;
        *(uint4*)&sA[r * pitch + c * 8] = *(const uint4*)&Ag[(m0 + r) * K + c * 8];
        *(uint4*)&sB[r * pitch + c * 8] = *(const uint4*)&Bg[(size_t)r * K + c * 8];
    }
    __syncthreads();

    int w = tid >> 5;
    wmma::fragment<wmma::accumulator, 16, 16, 16, float> acc[8];
    #pragma unroll
    for (int n = 0; n < 8; n++) wmma::fill_fragment(acc[n], 0.f);

    for (int k = 0; k < K; k += 16) {
        wmma::fragment<wmma::matrix_a, 16, 16, 16, __nv_bfloat16, wmma::row_major> fa;
        wmma::load_matrix_sync(fa, &sA[(w * 16) * pitch + k], pitch);
        #pragma unroll
        for (int n = 0; n < 8; n++) {
            wmma::fragment<wmma::matrix_b, 16, 16, 16, __nv_bfloat16, wmma::col_major> fb;
            wmma::load_matrix_sync(fb, &sB[(n * 16) * pitch + k], pitch);
            wmma::mma_sync(acc[n], fa, fb, acc[n]);
        }
    }

    // ---- epilogue: stage to smem, fused stats, fp16 store ----
    __syncthreads();
    float* Hs = (float*)smb;                       // [128][128] = 64 KB
    #pragma unroll
    for (int n = 0; n < 8; n++)
        wmma::store_matrix_sync(&Hs[(w * 16) * HID + n * 16], acc[n], HID,
                                wmma::mem_row_major);
    __syncthreads();

    __half* H  = (layer == 1) ? g_h1pre : g_h2pre;
    float*  st = (layer == 1) ? g_stats1 : g_stats2;

    int col = tid & 127, half = tid >> 7;
    float s = 0.f, ss = 0.f;
    #pragma unroll 8
    for (int r = 0; r < 64; r++) {
        float vv = Hs[(half * 64 + r) * HID + col];
        s += vv;
        ss += vv * vv;
    }
    atomicAdd(&st[col], s);
    atomicAdd(&st[HID + col], ss);

    for (int i = tid; i < 128 * 32; i += 256) {
        int r = i >> 5, c = i & 31;
        float4 f = ((const float4*)&Hs[r * HID])[c];
        __half2 h0 = __floats2half2_rn(f.x, f.y);
        __half2 h1 = __floats2half2_rn(f.z, f.w);
        uint2 o;
        o.x = *(uint32_t*)&h0;
        o.y = *(uint32_t*)&h1;
        ((uint2*)&H[(m0 + r) * HID])[c] = o;
    }
}

// ---------------- norm / readout ---------------------------------------------
// 2048 blocks x 64 rows; fp16 input.
__global__ void k_norm(int layer,
                       const float* __restrict__ gamma, const float* __restrict__ beta,
                       const float* __restrict__ alpha) {
    __shared__ float sRs[64];
    int j = threadIdx.x;
    int b = blockIdx.x;
    const float* stats = (layer == 1) ? g_stats1 : g_stats2;
    const __half* hpre = (layer == 1) ? g_h1pre : g_h2pre;
    int rcol   = (layer == 1) ? 0 : HID;
    int writeH = (layer == 1) ? 1 : 0;

    if (writeH && j < 64) sRs[j] = g_rs_src[b * 64 + j];
    __syncthreads();

    const float invN = 1.0f / (float)N_NODES;
    float mu  = stats[j] * invN;
    float ex2 = stats[HID + j] * invN;
    float al  = alpha[j];
    float var = ex2 + mu * mu * (al * al - 2.f * al);
    float istd = rsqrtf(var + EPSV);
    float ga = gamma[j] * istd;
    float be = beta[j];
    float amu = al * mu;

    int g = (b * 64) / P_NODES;
    const __half* in = &hpre[(size_t)b * 64 * HID];
    __half* out = &g_h1h[(size_t)b * 64 * HID];
    float rsum = 0.f;
    #pragma unroll 4
    for (int r = 0; r < 64; r++) {
        float v = __half2float(in[r * HID + j]);
        float c = (v - amu) * ga + be;
        float y = c > 0.f ? c : SLOPE * c;
        if (writeH) out[r * HID + j] = __float2half(y * sRs[r]);
        rsum += y;
    }
    atomicAdd(&g_r[g * (2 * HID) + rcol + j], rsum);
}

__global__ void k_final(const float* __restrict__ Wc, float* __restrict__ out) {
    int t = threadIdx.x;
    int b = t >> 4, o = t & 15;
    const float* rb = &g_r[b * 2 * HID];
    const float* wr = &Wc[o * 2 * HID];
    float s = 0.f;
    #pragma unroll 8
    for (int k = 0; k < 2 * HID; k++) s += rb[k] * wr[k];
    out[b * OUT_DIM + o] = s * (1.0f / (float)P_NODES);
}

// ---------------- launch -----------------------------------------------------

extern "C" void kernel_launch(void* const* d_in, const int* in_sizes, int n_in,
                              void* d_out, int out_size) {
    const float* features = (const float*)d_in[0];
    const float* ew       = (const float*)d_in[1];
    const int*   src      = (const int*)d_in[2];
    const int*   dst      = (const int*)d_in[3];
    const float* W1       = (const float*)d_in[4];
    const float* W2       = (const float*)d_in[5];
    const float* Wc       = (const float*)d_in[6];
    const float* gamma1   = (const float*)d_in[7];
    const float* beta1    = (const float*)d_in[8];
    const float* alpha1   = (const float*)d_in[9];
    const float* gamma2   = (const float*)d_in[10];
    const float* beta2    = (const float*)d_in[11];
    const float* alpha2   = (const float*)d_in[12];
    float* out = (float*)d_out;

    const int smem2 = 2 * 128 * (HID + 8) * 2;                     // 69632
    cudaFuncSetAttribute(k_gemm, cudaFuncAttributeMaxDynamicSharedMemorySize, smem2);

    k_zero<<<N_NODES / 256, 256>>>();
    k_build<<<E_EDGES / 1024, 256>>>(src, dst, ew);
    k_rs<<<N_NODES / 256, 256>>>();
    k_prep<<<1025, 256>>>(features, W1, W2);

    k_agg1<<<N_NODES / 32, 256>>>();
    k_gemm<<<N_NODES / 128, 256, 65536>>>(1);
    k_norm<<<2048, 128>>>(1, gamma1, beta1, alpha1);

    k_agg2<<<N_NODES / 32, 256>>>();
    k_gemm<<<N_NODES / 128, 256, smem2>>>(2);
    k_norm<<<2048, 128>>>(2, gamma2, beta2, alpha2);

    k_final<<<1, 512>>>(Wc, out);
}